// round 13
// baseline (speedup 1.0000x reference)
#include <cuda_runtime.h>
#include <cuda_bf16.h>
#include <cuda_fp16.h>
#include <cstdint>

#define Bc    2
#define Sc    2048
#define Hc    16
#define Dc    64
#define DMc   1024
#define NQKVc 3072
#define NQKc  2048
#define MROWS (Bc*Sc)
#define BH    (Bc*Hc)

// ---------------------------------------------------------------------------
__device__ __nv_bfloat16 g_Xh[(size_t)MROWS*DMc];
__device__ __nv_bfloat16 g_Xl[(size_t)MROWS*DMc];
__device__ __half        g_Xf[(size_t)MROWS*DMc];
__device__ __nv_bfloat16 g_Wh[(size_t)NQKc*DMc];
__device__ __nv_bfloat16 g_Wl[(size_t)NQKc*DMc];
__device__ __half        g_Wvf[(size_t)1024*DMc];

__device__ __nv_bfloat16 g_Qh[(size_t)BH*Sc*Dc];
__device__ __nv_bfloat16 g_Ql[(size_t)BH*Sc*Dc];
__device__ __nv_bfloat16 g_Kh[(size_t)BH*Sc*Dc];
__device__ __nv_bfloat16 g_Kl[(size_t)BH*Sc*Dc];
__device__ __half        g_Vt[(size_t)BH*Dc*Sc];

// ---------------------------------------------------------------------------
__device__ __forceinline__ uint32_t smem_u32(const void* p) {
    uint32_t a;
    asm("{ .reg .u64 t; cvta.to.shared.u64 t, %1; cvt.u32.u64 %0, t; }" : "=r"(a) : "l"(p));
    return a;
}
__device__ __forceinline__ void ldsm4(uint32_t& d0, uint32_t& d1, uint32_t& d2,
                                      uint32_t& d3, uint32_t addr) {
    asm volatile("ldmatrix.sync.aligned.m8n8.x4.shared.b16 {%0,%1,%2,%3}, [%4];"
                 : "=r"(d0), "=r"(d1), "=r"(d2), "=r"(d3) : "r"(addr));
}
__device__ __forceinline__ void mma_bf16(float* c, const uint32_t* a,
                                         uint32_t b0, uint32_t b1) {
    asm volatile(
        "mma.sync.aligned.m16n8k16.row.col.f32.bf16.bf16.f32 "
        "{%0,%1,%2,%3}, {%4,%5,%6,%7}, {%8,%9}, {%0,%1,%2,%3};"
        : "+f"(c[0]), "+f"(c[1]), "+f"(c[2]), "+f"(c[3])
        : "r"(a[0]), "r"(a[1]), "r"(a[2]), "r"(a[3]), "r"(b0), "r"(b1));
}
__device__ __forceinline__ void mma_f16(float* c, const uint32_t* a,
                                        uint32_t b0, uint32_t b1) {
    asm volatile(
        "mma.sync.aligned.m16n8k16.row.col.f32.f16.f16.f32 "
        "{%0,%1,%2,%3}, {%4,%5,%6,%7}, {%8,%9}, {%0,%1,%2,%3};"
        : "+f"(c[0]), "+f"(c[1]), "+f"(c[2]), "+f"(c[3])
        : "r"(a[0]), "r"(a[1]), "r"(a[2]), "r"(a[3]), "r"(b0), "r"(b1));
}
__device__ __forceinline__ uint32_t packh2(float f_lo, float f_hi) {
    uint32_t r;
    asm("cvt.rn.f16x2.f32 %0, %1, %2;" : "=r"(r) : "f"(f_hi), "f"(f_lo));
    return r;
}
__device__ __forceinline__ float ex2f(float x) {
    float r;
    asm("ex2.approx.f32 %0, %1;" : "=f"(r) : "f"(x));
    return r;
}
__device__ __forceinline__ uint32_t ex2h2(uint32_t x) {
    uint32_t r;
    asm("ex2.approx.f16x2 %0, %1;" : "=r"(r) : "r"(x));
    return r;
}
__device__ __forceinline__ void split2b(float x, __nv_bfloat16& h, __nv_bfloat16& l) {
    h = __float2bfloat16_rn(x);
    l = __float2bfloat16_rn(x - __bfloat162float(h));
}
__device__ __forceinline__ void cpa16(uint32_t dst, const void* src) {
    asm volatile("cp.async.cg.shared.global [%0], [%1], 16;" :: "r"(dst), "l"(src) : "memory");
}
#define CPA_COMMIT() asm volatile("cp.async.commit_group;" ::: "memory")
#define CPA_WAIT(n)  asm volatile("cp.async.wait_group %0;" :: "n"(n) : "memory")

// ---------------------------------------------------------------------------
__global__ __launch_bounds__(256) void split_x_kernel(const float* __restrict__ X) {
    size_t i = (size_t)blockIdx.x * 256 + threadIdx.x;
    float4 v = ((const float4*)X)[i];
    float xs[4] = {v.x, v.y, v.z, v.w};
    __nv_bfloat16 h[4], l[4];
    __half f[4];
    #pragma unroll
    for (int e = 0; e < 4; e++) { split2b(xs[e], h[e], l[e]); f[e] = __float2half_rn(xs[e]); }
    *(uint2*)&g_Xh[4 * i] = *(uint2*)h;
    *(uint2*)&g_Xl[4 * i] = *(uint2*)l;
    *(uint2*)&g_Xf[4 * i] = *(uint2*)f;
}

__global__ void split_w_kernel(const float* __restrict__ W) {
    __shared__ float tile[32][33];
    int n0 = blockIdx.x * 32, k0 = blockIdx.y * 32;
    int tx = threadIdx.x, ty = threadIdx.y;
    for (int i = ty; i < 32; i += 8)
        tile[i][tx] = W[(size_t)(k0 + i) * NQKVc + n0 + tx];
    __syncthreads();
    for (int i = ty; i < 32; i += 8) {
        float w = tile[tx][i];
        int col = n0 + i, k = k0 + tx;
        int hh = col / 192, rr = col - hh * 192;
        if (rr < 128) {
            __nv_bfloat16 h, l;
            split2b(w, h, l);
            size_t o = (size_t)(hh * 128 + rr) * DMc + k;
            g_Wh[o] = h; g_Wl[o] = l;
        } else {
            g_Wvf[(size_t)(hh * 64 + rr - 128) * DMc + k] = __float2half_rn(w);
        }
    }
}

// ---------------------------------------------------------------------------
// Fused projection kernel, heterogeneous grid (24, 32):
//   blockIdx.x <  16 : QK tile (bf16 3-product)
//   blockIdx.x >= 16 : V  tile (fp16 1-product)
// One launch -> SM scheduler interleaves both kinds; tails pack.
// ---------------------------------------------------------------------------
#define QPW     20
#define QTW     (128 * QPW)
#define QSTAGEW (4 * QTW)
#define QKV_SMEM (2 * QSTAGEW * 4)    // 81,920 B (covers both paths)

__device__ __forceinline__ void qk_block(uint32_t* sw, uint32_t sb,
                                         const float* __restrict__ bias,
                                         int n0, int m0) {
    const int tid  = threadIdx.x;
    const int lane = tid & 31;
    const int wid  = tid >> 5;
    const int wm   = wid & 3;
    const int wn   = wid >> 2;

    float acc[2][8][4];
    #pragma unroll
    for (int mt = 0; mt < 2; mt++)
        #pragma unroll
        for (int j = 0; j < 8; j++)
            #pragma unroll
            for (int e = 0; e < 4; e++) acc[mt][j][e] = 0.f;

    const uint32_t a_row = lane & 15;
    const uint32_t a_kw  = (lane & 16) >> 2;
    const uint32_t b_row = (lane & 7) + ((lane & 16) >> 1);
    const uint32_t b_kw  = (lane & 8) >> 1;

    const uint4* srcs[4] = {
        (const uint4*)g_Xh + (size_t)m0 * 128,
        (const uint4*)g_Xl + (size_t)m0 * 128,
        (const uint4*)g_Wh + (size_t)n0 * 128,
        (const uint4*)g_Wl + (size_t)n0 * 128};

    auto load_chunk = [&](int buf, int kc) {
        uint32_t base = sb + (buf * QSTAGEW) * 4;
        #pragma unroll
        for (int t = tid; t < 2048; t += 256) {
            int tl = t >> 9, rem = t & 511, r = rem >> 2, q = rem & 3;
            cpa16(base + (tl * QTW + r * QPW + q * 4) * 4,
                  srcs[tl] + (size_t)r * 128 + kc * 4 + q);
        }
    };

    load_chunk(0, 0);
    CPA_COMMIT();

    for (int kc = 0; kc < DMc / 32; kc++) {
        int buf = kc & 1;
        if (kc + 1 < DMc / 32) { load_chunk(buf ^ 1, kc + 1); CPA_COMMIT(); CPA_WAIT(1); }
        else                   { CPA_WAIT(0); }
        __syncthreads();

        uint32_t stage = sb + (buf * QSTAGEW) * 4;
        #pragma unroll
        for (int s = 0; s < 2; s++) {
            uint32_t axh[2][4], axl[2][4];
            #pragma unroll
            for (int mt = 0; mt < 2; mt++) {
                uint32_t ra = ((wm * 32 + mt * 16 + a_row) * QPW + s * 8 + a_kw) * 4;
                ldsm4(axh[mt][0], axh[mt][1], axh[mt][2], axh[mt][3], stage + ra);
                ldsm4(axl[mt][0], axl[mt][1], axl[mt][2], axl[mt][3], stage + QTW * 4 + ra);
            }
            #pragma unroll
            for (int j2 = 0; j2 < 4; j2++) {
                uint32_t rb = ((wn * 64 + j2 * 16 + b_row) * QPW + s * 8 + b_kw) * 4;
                uint32_t bh0, bh1, bh2, bh3, bl0, bl1, bl2, bl3;
                ldsm4(bh0, bh1, bh2, bh3, stage + 2 * QTW * 4 + rb);
                ldsm4(bl0, bl1, bl2, bl3, stage + 3 * QTW * 4 + rb);
                #pragma unroll
                for (int mt = 0; mt < 2; mt++) {
                    mma_bf16(acc[mt][2 * j2],     axh[mt], bh0, bh1);
                    mma_bf16(acc[mt][2 * j2 + 1], axh[mt], bh2, bh3);
                    mma_bf16(acc[mt][2 * j2],     axh[mt], bl0, bl1);
                    mma_bf16(acc[mt][2 * j2 + 1], axh[mt], bl2, bl3);
                    mma_bf16(acc[mt][2 * j2],     axl[mt], bh0, bh1);
                    mma_bf16(acc[mt][2 * j2 + 1], axl[mt], bh2, bh3);
                }
            }
        }
        __syncthreads();
    }

    float* Cs = (float*)sw;
    #pragma unroll
    for (int mt = 0; mt < 2; mt++) {
        #pragma unroll
        for (int j = 0; j < 8; j++) {
            #pragma unroll
            for (int e = 0; e < 4; e++) {
                int rl = wm * 32 + mt * 16 + (lane >> 2) + (e >> 1) * 8;
                int cl = wn * 64 + j * 8 + 2 * (lane & 3) + (e & 1);
                int cg = n0 + cl;
                int bidx = (cg >> 7) * 192 + (cg & 127);
                Cs[rl * 129 + cl] = acc[mt][j][e] + __ldg(&bias[bidx]);
            }
        }
    }
    __syncthreads();

    const int b  = (m0 >> 11);
    const int s0 = m0 & 2047;

    for (int idx = tid; idx < 16384; idx += 256) {
        int r = idx >> 7, c = idx & 127;
        int cg = n0 + c;
        int hh = cg >> 7, rr = cg & 127;
        float v = Cs[r * 129 + c];
        int bh = b * Hc + hh;
        __nv_bfloat16 h, l;
        if (rr < 64) {
            split2b(11.5415603272f * v, h, l);   // 8*log2(e) folded into Q
            size_t o = ((size_t)bh * Sc + s0 + r) * Dc + rr;
            g_Qh[o] = h; g_Ql[o] = l;
        } else {
            split2b(v, h, l);
            size_t o = ((size_t)bh * Sc + s0 + r) * Dc + rr - 64;
            g_Kh[o] = h; g_Kl[o] = l;
        }
    }
}

#define VQW 20
#define VTW (128 * VQW)

__device__ __forceinline__ void v_block(uint32_t* sw, uint32_t sb,
                                        const float* __restrict__ bias,
                                        int n0, int m0) {
    const int tid  = threadIdx.x;
    const int lane = tid & 31;
    const int wid  = tid >> 5;
    const int wm   = wid & 3;
    const int wn   = wid >> 2;

    float acc[2][8][4];
    #pragma unroll
    for (int mt = 0; mt < 2; mt++)
        #pragma unroll
        for (int j = 0; j < 8; j++)
            #pragma unroll
            for (int e = 0; e < 4; e++) acc[mt][j][e] = 0.f;

    const uint32_t a_row = lane & 15;
    const uint32_t a_kw  = (lane & 16) >> 2;
    const uint32_t b_row = (lane & 7) + ((lane & 16) >> 1);
    const uint32_t b_kw  = (lane & 8) >> 1;

    const uint4* srcA = (const uint4*)g_Xf  + (size_t)m0 * 128;
    const uint4* srcB = (const uint4*)g_Wvf + (size_t)n0 * 128;

    const int VSTAGEW = 2 * VTW;
    auto load_chunk = [&](int buf, int kc) {
        uint32_t base = sb + (buf * VSTAGEW) * 4;
        #pragma unroll
        for (int t = tid; t < 1024; t += 256) {
            int tl = t >> 9, rem = t & 511, r = rem >> 2, q = rem & 3;
            const uint4* src = (tl == 0 ? srcA : srcB) + (size_t)r * 128 + kc * 4 + q;
            cpa16(base + (tl * VTW + r * VQW + q * 4) * 4, src);
        }
    };

    load_chunk(0, 0);
    CPA_COMMIT();

    for (int kc = 0; kc < DMc / 32; kc++) {
        int buf = kc & 1;
        if (kc + 1 < DMc / 32) { load_chunk(buf ^ 1, kc + 1); CPA_COMMIT(); CPA_WAIT(1); }
        else                   { CPA_WAIT(0); }
        __syncthreads();

        uint32_t stage = sb + (buf * VSTAGEW) * 4;
        #pragma unroll
        for (int s = 0; s < 2; s++) {
            uint32_t af[2][4];
            #pragma unroll
            for (int mt = 0; mt < 2; mt++) {
                uint32_t ra = ((wm * 32 + mt * 16 + a_row) * VQW + s * 8 + a_kw) * 4;
                ldsm4(af[mt][0], af[mt][1], af[mt][2], af[mt][3], stage + ra);
            }
            #pragma unroll
            for (int j2 = 0; j2 < 4; j2++) {
                uint32_t rb = ((wn * 64 + j2 * 16 + b_row) * VQW + s * 8 + b_kw) * 4;
                uint32_t b0, b1, b2, b3;
                ldsm4(b0, b1, b2, b3, stage + VTW * 4 + rb);
                #pragma unroll
                for (int mt = 0; mt < 2; mt++) {
                    mma_f16(acc[mt][2 * j2],     af[mt], b0, b1);
                    mma_f16(acc[mt][2 * j2 + 1], af[mt], b2, b3);
                }
            }
        }
        __syncthreads();
    }

    __half* Cs = (__half*)sw;
    #pragma unroll
    for (int mt = 0; mt < 2; mt++) {
        #pragma unroll
        for (int j = 0; j < 8; j++) {
            #pragma unroll
            for (int e = 0; e < 4; e++) {
                int rl = wm * 32 + mt * 16 + (lane >> 2) + (e >> 1) * 8;
                int cl = wn * 64 + j * 8 + 2 * (lane & 3) + (e & 1);
                int cg = n0 + cl;
                int bidx = (cg >> 6) * 192 + 128 + (cg & 63);
                Cs[rl * 132 + cl] = __float2half_rn(acc[mt][j][e] + __ldg(&bias[bidx]));
            }
        }
    }
    __syncthreads();

    const int b  = (m0 >> 11);
    const int s0 = m0 & 2047;
    {
        int cgrp = tid >> 7;
        int sr   = tid & 127;
        #pragma unroll 2
        for (int cp = 0; cp < 64; cp++) {
            int c  = cp * 2 + cgrp;
            int cg = n0 + c;
            int hh = cg >> 6, d = cg & 63;
            g_Vt[((size_t)(b * Hc + hh) * Dc + d) * Sc + s0 + sr] = Cs[sr * 132 + c];
        }
    }
}

__global__ __launch_bounds__(256, 2) void qkv_fused_kernel(const float* __restrict__ bias) {
    extern __shared__ uint32_t sw[];
    const uint32_t sb = smem_u32(sw);
    const int m0 = blockIdx.y * 128;
    if (blockIdx.x < 16) qk_block(sw, sb, bias, blockIdx.x * 128, m0);
    else                 v_block(sw, sb, bias, (blockIdx.x - 16) * 128, m0);
}

// ---------------------------------------------------------------------------
// Attention FA2 (unchanged from R12).
// ---------------------------------------------------------------------------
#define KPW 36
#define KH0 0
#define KL0 (64 * KPW)
#define VF0 (2 * 64 * KPW)
#define ABUFW (3 * 64 * KPW)
#define NSTAGE 3
#define ATTN_SMEM (NSTAGE * ABUFW * 4)

__global__ __launch_bounds__(256, 2) void attn_kernel(float* __restrict__ out) {
    extern __shared__ uint32_t sw[];
    const uint32_t sb = smem_u32(sw);

    const int qt = blockIdx.x, h = blockIdx.y, b = blockIdx.z;
    const int bh = b * Hc + h;
    const int tid = threadIdx.x;
    const int lane = tid & 31;
    const int wid = tid >> 5;
    const int qg = qt * 128 + wid * 16;
    const int NT = Sc / 64;

    const uint4* Kh4 = (const uint4*)g_Kh + (size_t)bh * Sc * 8;
    const uint4* Kl4 = (const uint4*)g_Kl + (size_t)bh * Sc * 8;
    const uint4* Vf4 = (const uint4*)g_Vt + (size_t)bh * Dc * 256;

    auto load_kv = [&](int stg, int kt) {
        uint32_t base = sb + (stg * ABUFW) * 4;
        int kv0 = kt * 64;
        #pragma unroll
        for (int t = tid; t < 1536; t += 256) {
            int sec = t >> 9, rem = t & 511;
            int r = rem >> 3, q = rem & 7;
            if (sec == 0)
                cpa16(base + (KH0 + r * KPW + q * 4) * 4, Kh4 + (size_t)(kv0 + r) * 8 + q);
            else if (sec == 1)
                cpa16(base + (KL0 + r * KPW + q * 4) * 4, Kl4 + (size_t)(kv0 + r) * 8 + q);
            else
                cpa16(base + (VF0 + r * KPW + q * 4) * 4, Vf4 + (size_t)r * 256 + kt * 8 + q);
        }
    };

    uint32_t qh[4][4], ql[4][4];
    {
        const uint32_t* Qhw = (const uint32_t*)g_Qh + (size_t)bh * Sc * 32;
        const uint32_t* Qlw = (const uint32_t*)g_Ql + (size_t)bh * Sc * 32;
        int r0 = qg + (lane >> 2);
        #pragma unroll
        for (int s = 0; s < 4; s++) {
            int w0 = s * 8 + (lane & 3);
            qh[s][0] = Qhw[(size_t)r0 * 32 + w0];
            qh[s][1] = Qhw[(size_t)(r0 + 8) * 32 + w0];
            qh[s][2] = Qhw[(size_t)r0 * 32 + w0 + 4];
            qh[s][3] = Qhw[(size_t)(r0 + 8) * 32 + w0 + 4];
            ql[s][0] = Qlw[(size_t)r0 * 32 + w0];
            ql[s][1] = Qlw[(size_t)(r0 + 8) * 32 + w0];
            ql[s][2] = Qlw[(size_t)r0 * 32 + w0 + 4];
            ql[s][3] = Qlw[(size_t)(r0 + 8) * 32 + w0 + 4];
        }
    }

    float o[8][4];
    #pragma unroll
    for (int nd = 0; nd < 8; nd++)
        #pragma unroll
        for (int e = 0; e < 4; e++) o[nd][e] = 0.f;
    float lacc[4] = {0.f, 0.f, 0.f, 0.f};
    float m0 = -1e30f, m1 = -1e30f;

    const uint32_t ones_b = (lane < 4) ? 0x3C003C00u : 0u;

    const uint32_t f_row = (lane & 7) + ((lane & 16) >> 1);
    const uint32_t f_kw  = (lane & 8) >> 1;

    load_kv(0, 0); CPA_COMMIT();
    load_kv(1, 1); CPA_COMMIT();

    for (int kt = 0; kt < NT; kt++) {
        if (kt == NT - 1) { CPA_WAIT(0); } else { CPA_WAIT(1); }
        __syncthreads();
        if (kt + 2 < NT) { load_kv((kt + 2) % NSTAGE, kt + 2); CPA_COMMIT(); }

        uint32_t stage = sb + ((kt % NSTAGE) * ABUFW) * 4;

        float sc[8][4];
        #pragma unroll
        for (int j = 0; j < 8; j++)
            #pragma unroll
            for (int e = 0; e < 4; e++) sc[j][e] = 0.f;

        #pragma unroll
        for (int j2 = 0; j2 < 4; j2++) {
            uint32_t rbase = (j2 * 16 + f_row) * KPW;
            #pragma unroll
            for (int s = 0; s < 4; s++) {
                uint32_t ra = stage + (rbase + s * 8 + f_kw) * 4;
                uint32_t bh0, bh1, bh2, bh3, bl0, bl1, bl2, bl3;
                ldsm4(bh0, bh1, bh2, bh3, ra + KH0 * 4);
                ldsm4(bl0, bl1, bl2, bl3, ra + KL0 * 4);
                mma_bf16(sc[2 * j2],     qh[s], bh0, bh1);
                mma_bf16(sc[2 * j2 + 1], qh[s], bh2, bh3);
                mma_bf16(sc[2 * j2],     qh[s], bl0, bl1);
                mma_bf16(sc[2 * j2 + 1], qh[s], bl2, bl3);
                mma_bf16(sc[2 * j2],     ql[s], bh0, bh1);
                mma_bf16(sc[2 * j2 + 1], ql[s], bh2, bh3);
            }
        }

        float tm0 = -1e30f, tm1 = -1e30f;
        #pragma unroll
        for (int j = 0; j < 8; j++) {
            tm0 = fmaxf(tm0, fmaxf(sc[j][0], sc[j][1]));
            tm1 = fmaxf(tm1, fmaxf(sc[j][2], sc[j][3]));
        }
        tm0 = fmaxf(tm0, __shfl_xor_sync(0xffffffffu, tm0, 1));
        tm0 = fmaxf(tm0, __shfl_xor_sync(0xffffffffu, tm0, 2));
        tm1 = fmaxf(tm1, __shfl_xor_sync(0xffffffffu, tm1, 1));
        tm1 = fmaxf(tm1, __shfl_xor_sync(0xffffffffu, tm1, 2));
        float mn0 = fmaxf(m0, tm0), mn1 = fmaxf(m1, tm1);
        float c0 = ex2f(m0 - mn0), c1 = ex2f(m1 - mn1);

        uint32_t pk[8][2];
        #pragma unroll
        for (int j = 0; j < 8; j++) {
            pk[j][0] = ex2h2(packh2(sc[j][0] - mn0, sc[j][1] - mn0));
            pk[j][1] = ex2h2(packh2(sc[j][2] - mn1, sc[j][3] - mn1));
        }
        m0 = mn0; m1 = mn1;
        #pragma unroll
        for (int nd = 0; nd < 8; nd++) {
            o[nd][0] *= c0; o[nd][1] *= c0;
            o[nd][2] *= c1; o[nd][3] *= c1;
        }
        lacc[0] *= c0; lacc[1] *= c0;
        lacc[2] *= c1; lacc[3] *= c1;

        #pragma unroll
        for (int g = 0; g < 4; g++) {
            uint32_t rbase = (g * 16 + f_row) * KPW;
            #pragma unroll
            for (int t = 0; t < 4; t++) {
                uint32_t ra = stage + (rbase + t * 8 + f_kw) * 4 + VF0 * 4;
                uint32_t v0, v1, v2, v3;
                ldsm4(v0, v1, v2, v3, ra);
                uint32_t a[4] = {pk[2 * t][0], pk[2 * t][1], pk[2 * t + 1][0], pk[2 * t + 1][1]};
                mma_f16(o[2 * g],     a, v0, v1);
                mma_f16(o[2 * g + 1], a, v2, v3);
            }
            uint32_t al[4] = {pk[2 * g][0], pk[2 * g][1], pk[2 * g + 1][0], pk[2 * g + 1][1]};
            mma_f16(lacc, al, ones_b, ones_b);
        }
    }

    float l0 = __shfl_sync(0xffffffffu, lacc[0], lane & ~3);
    float l1 = __shfl_sync(0xffffffffu, lacc[2], lane & ~3);
    float inv0 = 1.0f / l0, inv1 = 1.0f / l1;
    int r0 = qg + (lane >> 2);
    #pragma unroll
    for (int nd = 0; nd < 8; nd++) {
        int d = h * Dc + nd * 8 + 2 * (lane & 3);
        float2 v0 = make_float2(o[nd][0] * inv0, o[nd][1] * inv0);
        float2 v1 = make_float2(o[nd][2] * inv1, o[nd][3] * inv1);
        *(float2*)(out + ((size_t)b * Sc + r0) * 1024 + d)     = v0;
        *(float2*)(out + ((size_t)b * Sc + r0 + 8) * 1024 + d) = v1;
    }
}

// ---------------------------------------------------------------------------
extern "C" void kernel_launch(void* const* d_in, const int* in_sizes, int n_in,
                              void* d_out, int out_size) {
    const float* X    = (const float*)d_in[0];
    const float* W    = (const float*)d_in[1];
    const float* bias = (const float*)d_in[2];
    float* out = (float*)d_out;

    split_x_kernel<<<(MROWS * DMc) / (256 * 4), 256>>>(X);
    split_w_kernel<<<dim3(NQKVc / 32, DMc / 32), dim3(32, 8)>>>(W);

    cudaFuncSetAttribute(qkv_fused_kernel, cudaFuncAttributeMaxDynamicSharedMemorySize, QKV_SMEM);
    qkv_fused_kernel<<<dim3(24, MROWS / 128), 256, QKV_SMEM>>>(bias);

    cudaFuncSetAttribute(attn_kernel, cudaFuncAttributeMaxDynamicSharedMemorySize, ATTN_SMEM);
    attn_kernel<<<dim3(Sc / 128, Hc, Bc), 256, ATTN_SMEM>>>(out);
}

// round 14
// speedup vs baseline: 1.0213x; 1.0213x over previous
#include <cuda_runtime.h>
#include <cuda_bf16.h>
#include <cuda_fp16.h>
#include <cstdint>

#define Bc    2
#define Sc    2048
#define Hc    16
#define Dc    64
#define DMc   1024
#define NQKVc 3072
#define NQKc  2048
#define MROWS (Bc*Sc)
#define BH    (Bc*Hc)

// ---------------------------------------------------------------------------
__device__ __nv_bfloat16 g_Xh[(size_t)MROWS*DMc];
__device__ __nv_bfloat16 g_Xl[(size_t)MROWS*DMc];
__device__ __half        g_Xf[(size_t)MROWS*DMc];
__device__ __nv_bfloat16 g_Wh[(size_t)NQKc*DMc];
__device__ __nv_bfloat16 g_Wl[(size_t)NQKc*DMc];
__device__ __half        g_Wvf[(size_t)1024*DMc];

__device__ __nv_bfloat16 g_Qh[(size_t)BH*Sc*Dc];
__device__ __nv_bfloat16 g_Ql[(size_t)BH*Sc*Dc];
__device__ __nv_bfloat16 g_Kh[(size_t)BH*Sc*Dc];
__device__ __nv_bfloat16 g_Kl[(size_t)BH*Sc*Dc];
__device__ __half        g_Vt[(size_t)BH*Dc*Sc];

// ---------------------------------------------------------------------------
__device__ __forceinline__ uint32_t smem_u32(const void* p) {
    uint32_t a;
    asm("{ .reg .u64 t; cvta.to.shared.u64 t, %1; cvt.u32.u64 %0, t; }" : "=r"(a) : "l"(p));
    return a;
}
__device__ __forceinline__ void ldsm4(uint32_t& d0, uint32_t& d1, uint32_t& d2,
                                      uint32_t& d3, uint32_t addr) {
    asm volatile("ldmatrix.sync.aligned.m8n8.x4.shared.b16 {%0,%1,%2,%3}, [%4];"
                 : "=r"(d0), "=r"(d1), "=r"(d2), "=r"(d3) : "r"(addr));
}
__device__ __forceinline__ void mma_bf16(float* c, const uint32_t* a,
                                         uint32_t b0, uint32_t b1) {
    asm volatile(
        "mma.sync.aligned.m16n8k16.row.col.f32.bf16.bf16.f32 "
        "{%0,%1,%2,%3}, {%4,%5,%6,%7}, {%8,%9}, {%0,%1,%2,%3};"
        : "+f"(c[0]), "+f"(c[1]), "+f"(c[2]), "+f"(c[3])
        : "r"(a[0]), "r"(a[1]), "r"(a[2]), "r"(a[3]), "r"(b0), "r"(b1));
}
__device__ __forceinline__ void mma_f16(float* c, const uint32_t* a,
                                        uint32_t b0, uint32_t b1) {
    asm volatile(
        "mma.sync.aligned.m16n8k16.row.col.f32.f16.f16.f32 "
        "{%0,%1,%2,%3}, {%4,%5,%6,%7}, {%8,%9}, {%0,%1,%2,%3};"
        : "+f"(c[0]), "+f"(c[1]), "+f"(c[2]), "+f"(c[3])
        : "r"(a[0]), "r"(a[1]), "r"(a[2]), "r"(a[3]), "r"(b0), "r"(b1));
}
__device__ __forceinline__ uint32_t packh2(float f_lo, float f_hi) {
    uint32_t r;
    asm("cvt.rn.f16x2.f32 %0, %1, %2;" : "=r"(r) : "f"(f_hi), "f"(f_lo));
    return r;
}
__device__ __forceinline__ float ex2f(float x) {
    float r;
    asm("ex2.approx.f32 %0, %1;" : "=f"(r) : "f"(x));
    return r;
}
__device__ __forceinline__ uint32_t ex2h2(uint32_t x) {
    uint32_t r;
    asm("ex2.approx.f16x2 %0, %1;" : "=r"(r) : "r"(x));
    return r;
}
__device__ __forceinline__ void split2b(float x, __nv_bfloat16& h, __nv_bfloat16& l) {
    h = __float2bfloat16_rn(x);
    l = __float2bfloat16_rn(x - __bfloat162float(h));
}
__device__ __forceinline__ void cpa16(uint32_t dst, const void* src) {
    asm volatile("cp.async.cg.shared.global [%0], [%1], 16;" :: "r"(dst), "l"(src) : "memory");
}
#define CPA_COMMIT() asm volatile("cp.async.commit_group;" ::: "memory")
#define CPA_WAIT(n)  asm volatile("cp.async.wait_group %0;" :: "n"(n) : "memory")

// ---------------------------------------------------------------------------
__global__ __launch_bounds__(256) void split_x_kernel(const float* __restrict__ X) {
    size_t i = (size_t)blockIdx.x * 256 + threadIdx.x;
    float4 v = ((const float4*)X)[i];
    float xs[4] = {v.x, v.y, v.z, v.w};
    __nv_bfloat16 h[4], l[4];
    __half f[4];
    #pragma unroll
    for (int e = 0; e < 4; e++) { split2b(xs[e], h[e], l[e]); f[e] = __float2half_rn(xs[e]); }
    *(uint2*)&g_Xh[4 * i] = *(uint2*)h;
    *(uint2*)&g_Xl[4 * i] = *(uint2*)l;
    *(uint2*)&g_Xf[4 * i] = *(uint2*)f;
}

__global__ void split_w_kernel(const float* __restrict__ W) {
    __shared__ float tile[32][33];
    int n0 = blockIdx.x * 32, k0 = blockIdx.y * 32;
    int tx = threadIdx.x, ty = threadIdx.y;
    for (int i = ty; i < 32; i += 8)
        tile[i][tx] = W[(size_t)(k0 + i) * NQKVc + n0 + tx];
    __syncthreads();
    for (int i = ty; i < 32; i += 8) {
        float w = tile[tx][i];
        int col = n0 + i, k = k0 + tx;
        int hh = col / 192, rr = col - hh * 192;
        if (rr < 128) {
            __nv_bfloat16 h, l;
            split2b(w, h, l);
            size_t o = (size_t)(hh * 128 + rr) * DMc + k;
            g_Wh[o] = h; g_Wl[o] = l;
        } else {
            g_Wvf[(size_t)(hh * 64 + rr - 128) * DMc + k] = __float2half_rn(w);
        }
    }
}

// ---------------------------------------------------------------------------
// QK GEMM: bf16 3-product, 2-stage cp.async (R12-identical).
// ---------------------------------------------------------------------------
#define QPW     20
#define QTW     (128 * QPW)
#define QSTAGEW (4 * QTW)
#define QKV_SMEM (2 * QSTAGEW * 4)

__global__ __launch_bounds__(256, 2) void qkv_mma_kernel(const float* __restrict__ bias) {
    extern __shared__ uint32_t sw[];
    const uint32_t sb = smem_u32(sw);

    const int tid  = threadIdx.x;
    const int lane = tid & 31;
    const int wid  = tid >> 5;
    const int wm   = wid & 3;
    const int wn   = wid >> 2;
    const int n0   = blockIdx.x * 128;
    const int m0   = blockIdx.y * 128;

    float acc[2][8][4];
    #pragma unroll
    for (int mt = 0; mt < 2; mt++)
        #pragma unroll
        for (int j = 0; j < 8; j++)
            #pragma unroll
            for (int e = 0; e < 4; e++) acc[mt][j][e] = 0.f;

    const uint32_t a_row = lane & 15;
    const uint32_t a_kw  = (lane & 16) >> 2;
    const uint32_t b_row = (lane & 7) + ((lane & 16) >> 1);
    const uint32_t b_kw  = (lane & 8) >> 1;

    const uint4* srcs[4] = {
        (const uint4*)g_Xh + (size_t)m0 * 128,
        (const uint4*)g_Xl + (size_t)m0 * 128,
        (const uint4*)g_Wh + (size_t)n0 * 128,
        (const uint4*)g_Wl + (size_t)n0 * 128};

    auto load_chunk = [&](int buf, int kc) {
        uint32_t base = sb + (buf * QSTAGEW) * 4;
        #pragma unroll
        for (int t = tid; t < 2048; t += 256) {
            int tl = t >> 9, rem = t & 511, r = rem >> 2, q = rem & 3;
            cpa16(base + (tl * QTW + r * QPW + q * 4) * 4,
                  srcs[tl] + (size_t)r * 128 + kc * 4 + q);
        }
    };

    load_chunk(0, 0);
    CPA_COMMIT();

    for (int kc = 0; kc < DMc / 32; kc++) {
        int buf = kc & 1;
        if (kc + 1 < DMc / 32) { load_chunk(buf ^ 1, kc + 1); CPA_COMMIT(); CPA_WAIT(1); }
        else                   { CPA_WAIT(0); }
        __syncthreads();

        uint32_t stage = sb + (buf * QSTAGEW) * 4;
        #pragma unroll
        for (int s = 0; s < 2; s++) {
            uint32_t axh[2][4], axl[2][4];
            #pragma unroll
            for (int mt = 0; mt < 2; mt++) {
                uint32_t ra = ((wm * 32 + mt * 16 + a_row) * QPW + s * 8 + a_kw) * 4;
                ldsm4(axh[mt][0], axh[mt][1], axh[mt][2], axh[mt][3], stage + ra);
                ldsm4(axl[mt][0], axl[mt][1], axl[mt][2], axl[mt][3], stage + QTW * 4 + ra);
            }
            #pragma unroll
            for (int j2 = 0; j2 < 4; j2++) {
                uint32_t rb = ((wn * 64 + j2 * 16 + b_row) * QPW + s * 8 + b_kw) * 4;
                uint32_t bh0, bh1, bh2, bh3, bl0, bl1, bl2, bl3;
                ldsm4(bh0, bh1, bh2, bh3, stage + 2 * QTW * 4 + rb);
                ldsm4(bl0, bl1, bl2, bl3, stage + 3 * QTW * 4 + rb);
                #pragma unroll
                for (int mt = 0; mt < 2; mt++) {
                    mma_bf16(acc[mt][2 * j2],     axh[mt], bh0, bh1);
                    mma_bf16(acc[mt][2 * j2 + 1], axh[mt], bh2, bh3);
                    mma_bf16(acc[mt][2 * j2],     axh[mt], bl0, bl1);
                    mma_bf16(acc[mt][2 * j2 + 1], axh[mt], bl2, bl3);
                    mma_bf16(acc[mt][2 * j2],     axl[mt], bh0, bh1);
                    mma_bf16(acc[mt][2 * j2 + 1], axl[mt], bh2, bh3);
                }
            }
        }
        __syncthreads();
    }

    float* Cs = (float*)sw;
    #pragma unroll
    for (int mt = 0; mt < 2; mt++) {
        #pragma unroll
        for (int j = 0; j < 8; j++) {
            #pragma unroll
            for (int e = 0; e < 4; e++) {
                int rl = wm * 32 + mt * 16 + (lane >> 2) + (e >> 1) * 8;
                int cl = wn * 64 + j * 8 + 2 * (lane & 3) + (e & 1);
                int cg = n0 + cl;
                int bidx = (cg >> 7) * 192 + (cg & 127);
                Cs[rl * 129 + cl] = acc[mt][j][e] + __ldg(&bias[bidx]);
            }
        }
    }
    __syncthreads();

    const int b  = (m0 >> 11);
    const int s0 = m0 & 2047;

    for (int idx = tid; idx < 16384; idx += 256) {
        int r = idx >> 7, c = idx & 127;
        int cg = n0 + c;
        int hh = cg >> 7, rr = cg & 127;
        float v = Cs[r * 129 + c];
        int bh = b * Hc + hh;
        __nv_bfloat16 h, l;
        if (rr < 64) {
            split2b(11.5415603272f * v, h, l);   // 8*log2(e) folded into Q
            size_t o = ((size_t)bh * Sc + s0 + r) * Dc + rr;
            g_Qh[o] = h; g_Ql[o] = l;
        } else {
            split2b(v, h, l);
            size_t o = ((size_t)bh * Sc + s0 + r) * Dc + rr - 64;
            g_Kh[o] = h; g_Kl[o] = l;
        }
    }
}

// ---------------------------------------------------------------------------
// V GEMM: fp16 single-product (R12-identical).
// ---------------------------------------------------------------------------
#define VQW     20
#define VTW     (128 * VQW)
#define VSTAGEW (2 * VTW)
#define VG_SMEM (2 * VSTAGEW * 4)

__global__ __launch_bounds__(256, 2) void v_mma_kernel(const float* __restrict__ bias) {
    extern __shared__ uint32_t sw[];
    const uint32_t sb = smem_u32(sw);

    const int tid  = threadIdx.x;
    const int lane = tid & 31;
    const int wid  = tid >> 5;
    const int wm   = wid & 3;
    const int wn   = wid >> 2;
    const int n0   = blockIdx.x * 128;
    const int m0   = blockIdx.y * 128;

    float acc[2][8][4];
    #pragma unroll
    for (int mt = 0; mt < 2; mt++)
        #pragma unroll
        for (int j = 0; j < 8; j++)
            #pragma unroll
            for (int e = 0; e < 4; e++) acc[mt][j][e] = 0.f;

    const uint32_t a_row = lane & 15;
    const uint32_t a_kw  = (lane & 16) >> 2;
    const uint32_t b_row = (lane & 7) + ((lane & 16) >> 1);
    const uint32_t b_kw  = (lane & 8) >> 1;

    const uint4* srcA = (const uint4*)g_Xf  + (size_t)m0 * 128;
    const uint4* srcB = (const uint4*)g_Wvf + (size_t)n0 * 128;

    auto load_chunk = [&](int buf, int kc) {
        uint32_t base = sb + (buf * VSTAGEW) * 4;
        #pragma unroll
        for (int t = tid; t < 1024; t += 256) {
            int tl = t >> 9, rem = t & 511, r = rem >> 2, q = rem & 3;
            const uint4* src = (tl == 0 ? srcA : srcB) + (size_t)r * 128 + kc * 4 + q;
            cpa16(base + (tl * VTW + r * VQW + q * 4) * 4, src);
        }
    };

    load_chunk(0, 0);
    CPA_COMMIT();

    for (int kc = 0; kc < DMc / 32; kc++) {
        int buf = kc & 1;
        if (kc + 1 < DMc / 32) { load_chunk(buf ^ 1, kc + 1); CPA_COMMIT(); CPA_WAIT(1); }
        else                   { CPA_WAIT(0); }
        __syncthreads();

        uint32_t stage = sb + (buf * VSTAGEW) * 4;
        #pragma unroll
        for (int s = 0; s < 2; s++) {
            uint32_t af[2][4];
            #pragma unroll
            for (int mt = 0; mt < 2; mt++) {
                uint32_t ra = ((wm * 32 + mt * 16 + a_row) * VQW + s * 8 + a_kw) * 4;
                ldsm4(af[mt][0], af[mt][1], af[mt][2], af[mt][3], stage + ra);
            }
            #pragma unroll
            for (int j2 = 0; j2 < 4; j2++) {
                uint32_t rb = ((wn * 64 + j2 * 16 + b_row) * VQW + s * 8 + b_kw) * 4;
                uint32_t b0, b1, b2, b3;
                ldsm4(b0, b1, b2, b3, stage + VTW * 4 + rb);
                #pragma unroll
                for (int mt = 0; mt < 2; mt++) {
                    mma_f16(acc[mt][2 * j2],     af[mt], b0, b1);
                    mma_f16(acc[mt][2 * j2 + 1], af[mt], b2, b3);
                }
            }
        }
        __syncthreads();
    }

    __half* Cs = (__half*)sw;
    #pragma unroll
    for (int mt = 0; mt < 2; mt++) {
        #pragma unroll
        for (int j = 0; j < 8; j++) {
            #pragma unroll
            for (int e = 0; e < 4; e++) {
                int rl = wm * 32 + mt * 16 + (lane >> 2) + (e >> 1) * 8;
                int cl = wn * 64 + j * 8 + 2 * (lane & 3) + (e & 1);
                int cg = n0 + cl;
                int bidx = (cg >> 6) * 192 + 128 + (cg & 63);
                Cs[rl * 132 + cl] = __float2half_rn(acc[mt][j][e] + __ldg(&bias[bidx]));
            }
        }
    }
    __syncthreads();

    const int b  = (m0 >> 11);
    const int s0 = m0 & 2047;
    {
        int cgrp = tid >> 7;
        int sr   = tid & 127;
        #pragma unroll 2
        for (int cp = 0; cp < 64; cp++) {
            int c  = cp * 2 + cgrp;
            int cg = n0 + c;
            int hh = cg >> 6, d = cg & 63;
            g_Vt[((size_t)(b * Hc + hh) * Dc + d) * Sc + s0 + sr] = Cs[sr * 132 + c];
        }
    }
}

// ---------------------------------------------------------------------------
// Attention FA2: KV tile 64, 4-stage cp.async with TWO tiles in flight,
// rescale-skip guard. QK 3-product bf16 (log2), ex2.f16x2, fp16 PV,
// l on tensor pipe.
// ---------------------------------------------------------------------------
#define KPW 36
#define KH0 0
#define KL0 (64 * KPW)
#define VF0 (2 * 64 * KPW)
#define ABUFW (3 * 64 * KPW)            // 6912 words = 27,648 B per stage
#define NSTAGE 4
#define ATTN_SMEM (NSTAGE * ABUFW * 4)  // 110,592 B

__global__ __launch_bounds__(256, 2) void attn_kernel(float* __restrict__ out) {
    extern __shared__ uint32_t sw[];
    const uint32_t sb = smem_u32(sw);

    const int qt = blockIdx.x, h = blockIdx.y, b = blockIdx.z;
    const int bh = b * Hc + h;
    const int tid = threadIdx.x;
    const int lane = tid & 31;
    const int wid = tid >> 5;
    const int qg = qt * 128 + wid * 16;
    const int NT = Sc / 64;

    const uint4* Kh4 = (const uint4*)g_Kh + (size_t)bh * Sc * 8;
    const uint4* Kl4 = (const uint4*)g_Kl + (size_t)bh * Sc * 8;
    const uint4* Vf4 = (const uint4*)g_Vt + (size_t)bh * Dc * 256;

    auto load_kv = [&](int stg, int kt) {
        uint32_t base = sb + (stg * ABUFW) * 4;
        int kv0 = kt * 64;
        #pragma unroll
        for (int t = tid; t < 1536; t += 256) {
            int sec = t >> 9, rem = t & 511;
            int r = rem >> 3, q = rem & 7;
            if (sec == 0)
                cpa16(base + (KH0 + r * KPW + q * 4) * 4, Kh4 + (size_t)(kv0 + r) * 8 + q);
            else if (sec == 1)
                cpa16(base + (KL0 + r * KPW + q * 4) * 4, Kl4 + (size_t)(kv0 + r) * 8 + q);
            else
                cpa16(base + (VF0 + r * KPW + q * 4) * 4, Vf4 + (size_t)r * 256 + kt * 8 + q);
        }
    };

    // ---- preload Q fragments (pre-scaled by 8*log2e) ----
    uint32_t qh[4][4], ql[4][4];
    {
        const uint32_t* Qhw = (const uint32_t*)g_Qh + (size_t)bh * Sc * 32;
        const uint32_t* Qlw = (const uint32_t*)g_Ql + (size_t)bh * Sc * 32;
        int r0 = qg + (lane >> 2);
        #pragma unroll
        for (int s = 0; s < 4; s++) {
            int w0 = s * 8 + (lane & 3);
            qh[s][0] = Qhw[(size_t)r0 * 32 + w0];
            qh[s][1] = Qhw[(size_t)(r0 + 8) * 32 + w0];
            qh[s][2] = Qhw[(size_t)r0 * 32 + w0 + 4];
            qh[s][3] = Qhw[(size_t)(r0 + 8) * 32 + w0 + 4];
            ql[s][0] = Qlw[(size_t)r0 * 32 + w0];
            ql[s][1] = Qlw[(size_t)(r0 + 8) * 32 + w0];
            ql[s][2] = Qlw[(size_t)r0 * 32 + w0 + 4];
            ql[s][3] = Qlw[(size_t)(r0 + 8) * 32 + w0 + 4];
        }
    }

    float o[8][4];
    #pragma unroll
    for (int nd = 0; nd < 8; nd++)
        #pragma unroll
        for (int e = 0; e < 4; e++) o[nd][e] = 0.f;
    float lacc[4] = {0.f, 0.f, 0.f, 0.f};
    float m0 = -1e30f, m1 = -1e30f;

    const uint32_t ones_b = (lane < 4) ? 0x3C003C00u : 0u;

    const uint32_t f_row = (lane & 7) + ((lane & 16) >> 1);
    const uint32_t f_kw  = (lane & 8) >> 1;

    load_kv(0, 0); CPA_COMMIT();
    load_kv(1, 1); CPA_COMMIT();
    load_kv(2, 2); CPA_COMMIT();

    for (int kt = 0; kt < NT; kt++) {
        if (kt < NT - 2)      { CPA_WAIT(2); }
        else if (kt == NT - 2){ CPA_WAIT(1); }
        else                  { CPA_WAIT(0); }
        __syncthreads();
        if (kt + 3 < NT) { load_kv((kt + 3) % NSTAGE, kt + 3); CPA_COMMIT(); }

        uint32_t stage = sb + ((kt % NSTAGE) * ABUFW) * 4;

        // ---- scores (log2-domain) ----
        float sc[8][4];
        #pragma unroll
        for (int j = 0; j < 8; j++)
            #pragma unroll
            for (int e = 0; e < 4; e++) sc[j][e] = 0.f;

        #pragma unroll
        for (int j2 = 0; j2 < 4; j2++) {
            uint32_t rbase = (j2 * 16 + f_row) * KPW;
            #pragma unroll
            for (int s = 0; s < 4; s++) {
                uint32_t ra = stage + (rbase + s * 8 + f_kw) * 4;
                uint32_t bh0, bh1, bh2, bh3, bl0, bl1, bl2, bl3;
                ldsm4(bh0, bh1, bh2, bh3, ra + KH0 * 4);
                ldsm4(bl0, bl1, bl2, bl3, ra + KL0 * 4);
                mma_bf16(sc[2 * j2],     qh[s], bh0, bh1);
                mma_bf16(sc[2 * j2 + 1], qh[s], bh2, bh3);
                mma_bf16(sc[2 * j2],     qh[s], bl0, bl1);
                mma_bf16(sc[2 * j2 + 1], qh[s], bl2, bl3);
                mma_bf16(sc[2 * j2],     ql[s], bh0, bh1);
                mma_bf16(sc[2 * j2 + 1], ql[s], bh2, bh3);
            }
        }

        // ---- online softmax (base-2) ----
        float tm0 = -1e30f, tm1 = -1e30f;
        #pragma unroll
        for (int j = 0; j < 8; j++) {
            tm0 = fmaxf(tm0, fmaxf(sc[j][0], sc[j][1]));
            tm1 = fmaxf(tm1, fmaxf(sc[j][2], sc[j][3]));
        }
        tm0 = fmaxf(tm0, __shfl_xor_sync(0xffffffffu, tm0, 1));
        tm0 = fmaxf(tm0, __shfl_xor_sync(0xffffffffu, tm0, 2));
        tm1 = fmaxf(tm1, __shfl_xor_sync(0xffffffffu, tm1, 1));
        tm1 = fmaxf(tm1, __shfl_xor_sync(0xffffffffu, tm1, 2));
        bool upd = (tm0 > m0) | (tm1 > m1);
        if (__any_sync(0xffffffffu, upd)) {
            float mn0 = fmaxf(m0, tm0), mn1 = fmaxf(m1, tm1);
            float c0 = ex2f(m0 - mn0), c1 = ex2f(m1 - mn1);
            m0 = mn0; m1 = mn1;
            #pragma unroll
            for (int nd = 0; nd < 8; nd++) {
                o[nd][0] *= c0; o[nd][1] *= c0;
                o[nd][2] *= c1; o[nd][3] *= c1;
            }
            lacc[0] *= c0; lacc[1] *= c0;
            lacc[2] *= c1; lacc[3] *= c1;
        }

        uint32_t pk[8][2];
        #pragma unroll
        for (int j = 0; j < 8; j++) {
            pk[j][0] = ex2h2(packh2(sc[j][0] - m0, sc[j][1] - m0));
            pk[j][1] = ex2h2(packh2(sc[j][2] - m1, sc[j][3] - m1));
        }

        // ---- O += P @ V; lacc mma interleaved ----
        #pragma unroll
        for (int g = 0; g < 4; g++) {
            uint32_t rbase = (g * 16 + f_row) * KPW;
            #pragma unroll
            for (int t = 0; t < 4; t++) {
                uint32_t ra = stage + (rbase + t * 8 + f_kw) * 4 + VF0 * 4;
                uint32_t v0, v1, v2, v3;
                ldsm4(v0, v1, v2, v3, ra);
                uint32_t a[4] = {pk[2 * t][0], pk[2 * t][1], pk[2 * t + 1][0], pk[2 * t + 1][1]};
                mma_f16(o[2 * g],     a, v0, v1);
                mma_f16(o[2 * g + 1], a, v2, v3);
            }
            uint32_t al[4] = {pk[2 * g][0], pk[2 * g][1], pk[2 * g + 1][0], pk[2 * g + 1][1]};
            mma_f16(lacc, al, ones_b, ones_b);
        }
    }

    float l0 = __shfl_sync(0xffffffffu, lacc[0], lane & ~3);
    float l1 = __shfl_sync(0xffffffffu, lacc[2], lane & ~3);
    float inv0 = 1.0f / l0, inv1 = 1.0f / l1;
    int r0 = qg + (lane >> 2);
    #pragma unroll
    for (int nd = 0; nd < 8; nd++) {
        int d = h * Dc + nd * 8 + 2 * (lane & 3);
        float2 v0 = make_float2(o[nd][0] * inv0, o[nd][1] * inv0);
        float2 v1 = make_float2(o[nd][2] * inv1, o[nd][3] * inv1);
        *(float2*)(out + ((size_t)b * Sc + r0) * 1024 + d)     = v0;
        *(float2*)(out + ((size_t)b * Sc + r0 + 8) * 1024 + d) = v1;
    }
}

// ---------------------------------------------------------------------------
extern "C" void kernel_launch(void* const* d_in, const int* in_sizes, int n_in,
                              void* d_out, int out_size) {
    const float* X    = (const float*)d_in[0];
    const float* W    = (const float*)d_in[1];
    const float* bias = (const float*)d_in[2];
    float* out = (float*)d_out;

    split_x_kernel<<<(MROWS * DMc) / (256 * 4), 256>>>(X);
    split_w_kernel<<<dim3(NQKVc / 32, DMc / 32), dim3(32, 8)>>>(W);

    cudaFuncSetAttribute(qkv_mma_kernel, cudaFuncAttributeMaxDynamicSharedMemorySize, QKV_SMEM);
    qkv_mma_kernel<<<dim3(NQKc / 128, MROWS / 128), 256, QKV_SMEM>>>(bias);

    cudaFuncSetAttribute(v_mma_kernel, cudaFuncAttributeMaxDynamicSharedMemorySize, VG_SMEM);
    v_mma_kernel<<<dim3(1024 / 128, MROWS / 128), 256, VG_SMEM>>>(bias);

    cudaFuncSetAttribute(attn_kernel, cudaFuncAttributeMaxDynamicSharedMemorySize, ATTN_SMEM);
    attn_kernel<<<dim3(Sc / 128, Hc, Bc), 256, ATTN_SMEM>>>(out);
}

// round 15
// speedup vs baseline: 1.0279x; 1.0065x over previous
#include <cuda_runtime.h>
#include <cuda_bf16.h>
#include <cuda_fp16.h>
#include <cstdint>

#define Bc    2
#define Sc    2048
#define Hc    16
#define Dc    64
#define DMc   1024
#define NQKVc 3072
#define NQKc  2048
#define MROWS (Bc*Sc)
#define BH    (Bc*Hc)

// ---------------------------------------------------------------------------
__device__ __nv_bfloat16 g_Xh[(size_t)MROWS*DMc];
__device__ __nv_bfloat16 g_Xl[(size_t)MROWS*DMc];
__device__ __half        g_Xf[(size_t)MROWS*DMc];
__device__ __nv_bfloat16 g_Wh[(size_t)NQKc*DMc];
__device__ __nv_bfloat16 g_Wl[(size_t)NQKc*DMc];
__device__ __half        g_Wvf[(size_t)1024*DMc];

__device__ __nv_bfloat16 g_Qh[(size_t)BH*Sc*Dc];
__device__ __nv_bfloat16 g_Ql[(size_t)BH*Sc*Dc];
__device__ __nv_bfloat16 g_Kh[(size_t)BH*Sc*Dc];
__device__ __nv_bfloat16 g_Kl[(size_t)BH*Sc*Dc];
__device__ __half        g_Vt[(size_t)BH*Dc*Sc];

// ---------------------------------------------------------------------------
__device__ __forceinline__ uint32_t smem_u32(const void* p) {
    uint32_t a;
    asm("{ .reg .u64 t; cvta.to.shared.u64 t, %1; cvt.u32.u64 %0, t; }" : "=r"(a) : "l"(p));
    return a;
}
__device__ __forceinline__ void ldsm4(uint32_t& d0, uint32_t& d1, uint32_t& d2,
                                      uint32_t& d3, uint32_t addr) {
    asm volatile("ldmatrix.sync.aligned.m8n8.x4.shared.b16 {%0,%1,%2,%3}, [%4];"
                 : "=r"(d0), "=r"(d1), "=r"(d2), "=r"(d3) : "r"(addr));
}
__device__ __forceinline__ void mma_bf16(float* c, const uint32_t* a,
                                         uint32_t b0, uint32_t b1) {
    asm volatile(
        "mma.sync.aligned.m16n8k16.row.col.f32.bf16.bf16.f32 "
        "{%0,%1,%2,%3}, {%4,%5,%6,%7}, {%8,%9}, {%0,%1,%2,%3};"
        : "+f"(c[0]), "+f"(c[1]), "+f"(c[2]), "+f"(c[3])
        : "r"(a[0]), "r"(a[1]), "r"(a[2]), "r"(a[3]), "r"(b0), "r"(b1));
}
__device__ __forceinline__ void mma_f16(float* c, const uint32_t* a,
                                        uint32_t b0, uint32_t b1) {
    asm volatile(
        "mma.sync.aligned.m16n8k16.row.col.f32.f16.f16.f32 "
        "{%0,%1,%2,%3}, {%4,%5,%6,%7}, {%8,%9}, {%0,%1,%2,%3};"
        : "+f"(c[0]), "+f"(c[1]), "+f"(c[2]), "+f"(c[3])
        : "r"(a[0]), "r"(a[1]), "r"(a[2]), "r"(a[3]), "r"(b0), "r"(b1));
}
__device__ __forceinline__ uint32_t packh2(float f_lo, float f_hi) {
    uint32_t r;
    asm("cvt.rn.f16x2.f32 %0, %1, %2;" : "=r"(r) : "f"(f_hi), "f"(f_lo));
    return r;
}
__device__ __forceinline__ float ex2f(float x) {
    float r;
    asm("ex2.approx.f32 %0, %1;" : "=f"(r) : "f"(x));
    return r;
}
__device__ __forceinline__ uint32_t ex2h2(uint32_t x) {
    uint32_t r;
    asm("ex2.approx.f16x2 %0, %1;" : "=r"(r) : "r"(x));
    return r;
}
__device__ __forceinline__ void split2b(float x, __nv_bfloat16& h, __nv_bfloat16& l) {
    h = __float2bfloat16_rn(x);
    l = __float2bfloat16_rn(x - __bfloat162float(h));
}
__device__ __forceinline__ void cpa16(uint32_t dst, const void* src) {
    asm volatile("cp.async.cg.shared.global [%0], [%1], 16;" :: "r"(dst), "l"(src) : "memory");
}
#define CPA_COMMIT() asm volatile("cp.async.commit_group;" ::: "memory")
#define CPA_WAIT(n)  asm volatile("cp.async.wait_group %0;" :: "n"(n) : "memory")

// ---------------------------------------------------------------------------
// Fused split kernel: blocks [0,4096) split X; blocks [4096,7168) split W.
// ---------------------------------------------------------------------------
__global__ __launch_bounds__(256) void split_xw_kernel(const float* __restrict__ X,
                                                       const float* __restrict__ W) {
    __shared__ float tile[32][33];
    int bid = blockIdx.x;
    if (bid < 4096) {
        size_t i = (size_t)bid * 256 + threadIdx.x;
        float4 v = ((const float4*)X)[i];
        float xs[4] = {v.x, v.y, v.z, v.w};
        __nv_bfloat16 h[4], l[4];
        __half f[4];
        #pragma unroll
        for (int e = 0; e < 4; e++) { split2b(xs[e], h[e], l[e]); f[e] = __float2half_rn(xs[e]); }
        *(uint2*)&g_Xh[4 * i] = *(uint2*)h;
        *(uint2*)&g_Xl[4 * i] = *(uint2*)l;
        *(uint2*)&g_Xf[4 * i] = *(uint2*)f;
    } else {
        int id = bid - 4096;                 // 0..3071
        int n0 = (id % 96) * 32, k0 = (id / 96) * 32;
        int tx = threadIdx.x & 31, ty = threadIdx.x >> 5;   // 32 x 8
        for (int i = ty; i < 32; i += 8)
            tile[i][tx] = W[(size_t)(k0 + i) * NQKVc + n0 + tx];
        __syncthreads();
        for (int i = ty; i < 32; i += 8) {
            float w = tile[tx][i];
            int col = n0 + i, k = k0 + tx;
            int hh = col / 192, rr = col - hh * 192;
            if (rr < 128) {
                __nv_bfloat16 h, l;
                split2b(w, h, l);
                size_t o = (size_t)(hh * 128 + rr) * DMc + k;
                g_Wh[o] = h; g_Wl[o] = l;
            } else {
                g_Wvf[(size_t)(hh * 64 + rr - 128) * DMc + k] = __float2half_rn(w);
            }
        }
    }
}

// ---------------------------------------------------------------------------
// QK GEMM: bf16 3-product, 2-stage cp.async (R12-identical).
// ---------------------------------------------------------------------------
#define QPW     20
#define QTW     (128 * QPW)
#define QSTAGEW (4 * QTW)
#define QKV_SMEM (2 * QSTAGEW * 4)

__global__ __launch_bounds__(256, 2) void qkv_mma_kernel(const float* __restrict__ bias) {
    extern __shared__ uint32_t sw[];
    const uint32_t sb = smem_u32(sw);

    const int tid  = threadIdx.x;
    const int lane = tid & 31;
    const int wid  = tid >> 5;
    const int wm   = wid & 3;
    const int wn   = wid >> 2;
    const int n0   = blockIdx.x * 128;
    const int m0   = blockIdx.y * 128;

    float acc[2][8][4];
    #pragma unroll
    for (int mt = 0; mt < 2; mt++)
        #pragma unroll
        for (int j = 0; j < 8; j++)
            #pragma unroll
            for (int e = 0; e < 4; e++) acc[mt][j][e] = 0.f;

    const uint32_t a_row = lane & 15;
    const uint32_t a_kw  = (lane & 16) >> 2;
    const uint32_t b_row = (lane & 7) + ((lane & 16) >> 1);
    const uint32_t b_kw  = (lane & 8) >> 1;

    const uint4* srcs[4] = {
        (const uint4*)g_Xh + (size_t)m0 * 128,
        (const uint4*)g_Xl + (size_t)m0 * 128,
        (const uint4*)g_Wh + (size_t)n0 * 128,
        (const uint4*)g_Wl + (size_t)n0 * 128};

    auto load_chunk = [&](int buf, int kc) {
        uint32_t base = sb + (buf * QSTAGEW) * 4;
        #pragma unroll
        for (int t = tid; t < 2048; t += 256) {
            int tl = t >> 9, rem = t & 511, r = rem >> 2, q = rem & 3;
            cpa16(base + (tl * QTW + r * QPW + q * 4) * 4,
                  srcs[tl] + (size_t)r * 128 + kc * 4 + q);
        }
    };

    load_chunk(0, 0);
    CPA_COMMIT();

    for (int kc = 0; kc < DMc / 32; kc++) {
        int buf = kc & 1;
        if (kc + 1 < DMc / 32) { load_chunk(buf ^ 1, kc + 1); CPA_COMMIT(); CPA_WAIT(1); }
        else                   { CPA_WAIT(0); }
        __syncthreads();

        uint32_t stage = sb + (buf * QSTAGEW) * 4;
        #pragma unroll
        for (int s = 0; s < 2; s++) {
            uint32_t axh[2][4], axl[2][4];
            #pragma unroll
            for (int mt = 0; mt < 2; mt++) {
                uint32_t ra = ((wm * 32 + mt * 16 + a_row) * QPW + s * 8 + a_kw) * 4;
                ldsm4(axh[mt][0], axh[mt][1], axh[mt][2], axh[mt][3], stage + ra);
                ldsm4(axl[mt][0], axl[mt][1], axl[mt][2], axl[mt][3], stage + QTW * 4 + ra);
            }
            #pragma unroll
            for (int j2 = 0; j2 < 4; j2++) {
                uint32_t rb = ((wn * 64 + j2 * 16 + b_row) * QPW + s * 8 + b_kw) * 4;
                uint32_t bh0, bh1, bh2, bh3, bl0, bl1, bl2, bl3;
                ldsm4(bh0, bh1, bh2, bh3, stage + 2 * QTW * 4 + rb);
                ldsm4(bl0, bl1, bl2, bl3, stage + 3 * QTW * 4 + rb);
                #pragma unroll
                for (int mt = 0; mt < 2; mt++) {
                    mma_bf16(acc[mt][2 * j2],     axh[mt], bh0, bh1);
                    mma_bf16(acc[mt][2 * j2 + 1], axh[mt], bh2, bh3);
                    mma_bf16(acc[mt][2 * j2],     axh[mt], bl0, bl1);
                    mma_bf16(acc[mt][2 * j2 + 1], axh[mt], bl2, bl3);
                    mma_bf16(acc[mt][2 * j2],     axl[mt], bh0, bh1);
                    mma_bf16(acc[mt][2 * j2 + 1], axl[mt], bh2, bh3);
                }
            }
        }
        __syncthreads();
    }

    float* Cs = (float*)sw;
    #pragma unroll
    for (int mt = 0; mt < 2; mt++) {
        #pragma unroll
        for (int j = 0; j < 8; j++) {
            #pragma unroll
            for (int e = 0; e < 4; e++) {
                int rl = wm * 32 + mt * 16 + (lane >> 2) + (e >> 1) * 8;
                int cl = wn * 64 + j * 8 + 2 * (lane & 3) + (e & 1);
                int cg = n0 + cl;
                int bidx = (cg >> 7) * 192 + (cg & 127);
                Cs[rl * 129 + cl] = acc[mt][j][e] + __ldg(&bias[bidx]);
            }
        }
    }
    __syncthreads();

    const int b  = (m0 >> 11);
    const int s0 = m0 & 2047;

    for (int idx = tid; idx < 16384; idx += 256) {
        int r = idx >> 7, c = idx & 127;
        int cg = n0 + c;
        int hh = cg >> 7, rr = cg & 127;
        float v = Cs[r * 129 + c];
        int bh = b * Hc + hh;
        __nv_bfloat16 h, l;
        if (rr < 64) {
            split2b(11.5415603272f * v, h, l);   // 8*log2(e) folded into Q
            size_t o = ((size_t)bh * Sc + s0 + r) * Dc + rr;
            g_Qh[o] = h; g_Ql[o] = l;
        } else {
            split2b(v, h, l);
            size_t o = ((size_t)bh * Sc + s0 + r) * Dc + rr - 64;
            g_Kh[o] = h; g_Kl[o] = l;
        }
    }
}

// ---------------------------------------------------------------------------
// V GEMM: fp16 single-product (R12-identical).
// ---------------------------------------------------------------------------
#define VQW     20
#define VTW     (128 * VQW)
#define VSTAGEW (2 * VTW)
#define VG_SMEM (2 * VSTAGEW * 4)

__global__ __launch_bounds__(256, 2) void v_mma_kernel(const float* __restrict__ bias) {
    extern __shared__ uint32_t sw[];
    const uint32_t sb = smem_u32(sw);

    const int tid  = threadIdx.x;
    const int lane = tid & 31;
    const int wid  = tid >> 5;
    const int wm   = wid & 3;
    const int wn   = wid >> 2;
    const int n0   = blockIdx.x * 128;
    const int m0   = blockIdx.y * 128;

    float acc[2][8][4];
    #pragma unroll
    for (int mt = 0; mt < 2; mt++)
        #pragma unroll
        for (int j = 0; j < 8; j++)
            #pragma unroll
            for (int e = 0; e < 4; e++) acc[mt][j][e] = 0.f;

    const uint32_t a_row = lane & 15;
    const uint32_t a_kw  = (lane & 16) >> 2;
    const uint32_t b_row = (lane & 7) + ((lane & 16) >> 1);
    const uint32_t b_kw  = (lane & 8) >> 1;

    const uint4* srcA = (const uint4*)g_Xf  + (size_t)m0 * 128;
    const uint4* srcB = (const uint4*)g_Wvf + (size_t)n0 * 128;

    auto load_chunk = [&](int buf, int kc) {
        uint32_t base = sb + (buf * VSTAGEW) * 4;
        #pragma unroll
        for (int t = tid; t < 1024; t += 256) {
            int tl = t >> 9, rem = t & 511, r = rem >> 2, q = rem & 3;
            const uint4* src = (tl == 0 ? srcA : srcB) + (size_t)r * 128 + kc * 4 + q;
            cpa16(base + (tl * VTW + r * VQW + q * 4) * 4, src);
        }
    };

    load_chunk(0, 0);
    CPA_COMMIT();

    for (int kc = 0; kc < DMc / 32; kc++) {
        int buf = kc & 1;
        if (kc + 1 < DMc / 32) { load_chunk(buf ^ 1, kc + 1); CPA_COMMIT(); CPA_WAIT(1); }
        else                   { CPA_WAIT(0); }
        __syncthreads();

        uint32_t stage = sb + (buf * VSTAGEW) * 4;
        #pragma unroll
        for (int s = 0; s < 2; s++) {
            uint32_t af[2][4];
            #pragma unroll
            for (int mt = 0; mt < 2; mt++) {
                uint32_t ra = ((wm * 32 + mt * 16 + a_row) * VQW + s * 8 + a_kw) * 4;
                ldsm4(af[mt][0], af[mt][1], af[mt][2], af[mt][3], stage + ra);
            }
            #pragma unroll
            for (int j2 = 0; j2 < 4; j2++) {
                uint32_t rb = ((wn * 64 + j2 * 16 + b_row) * VQW + s * 8 + b_kw) * 4;
                uint32_t b0, b1, b2, b3;
                ldsm4(b0, b1, b2, b3, stage + VTW * 4 + rb);
                #pragma unroll
                for (int mt = 0; mt < 2; mt++) {
                    mma_f16(acc[mt][2 * j2],     af[mt], b0, b1);
                    mma_f16(acc[mt][2 * j2 + 1], af[mt], b2, b3);
                }
            }
        }
        __syncthreads();
    }

    __half* Cs = (__half*)sw;
    #pragma unroll
    for (int mt = 0; mt < 2; mt++) {
        #pragma unroll
        for (int j = 0; j < 8; j++) {
            #pragma unroll
            for (int e = 0; e < 4; e++) {
                int rl = wm * 32 + mt * 16 + (lane >> 2) + (e >> 1) * 8;
                int cl = wn * 64 + j * 8 + 2 * (lane & 3) + (e & 1);
                int cg = n0 + cl;
                int bidx = (cg >> 6) * 192 + 128 + (cg & 63);
                Cs[rl * 132 + cl] = __float2half_rn(acc[mt][j][e] + __ldg(&bias[bidx]));
            }
        }
    }
    __syncthreads();

    const int b  = (m0 >> 11);
    const int s0 = m0 & 2047;
    {
        int cgrp = tid >> 7;
        int sr   = tid & 127;
        #pragma unroll 2
        for (int cp = 0; cp < 64; cp++) {
            int c  = cp * 2 + cgrp;
            int cg = n0 + c;
            int hh = cg >> 6, d = cg & 63;
            g_Vt[((size_t)(b * Hc + hh) * Dc + d) * Sc + s0 + sr] = Cs[sr * 132 + c];
        }
    }
}

// ---------------------------------------------------------------------------
// Attention FA2: KV tile 64, 4-stage cp.async (two tiles in flight),
// rescale-skip, software-pipelined LDSM->mma (double-buffered fragments).
// ---------------------------------------------------------------------------
#define KPW 36
#define KH0 0
#define KL0 (64 * KPW)
#define VF0 (2 * 64 * KPW)
#define ABUFW (3 * 64 * KPW)
#define NSTAGE 4
#define ATTN_SMEM (NSTAGE * ABUFW * 4)

__global__ __launch_bounds__(256, 2) void attn_kernel(float* __restrict__ out) {
    extern __shared__ uint32_t sw[];
    const uint32_t sb = smem_u32(sw);

    const int qt = blockIdx.x, h = blockIdx.y, b = blockIdx.z;
    const int bh = b * Hc + h;
    const int tid = threadIdx.x;
    const int lane = tid & 31;
    const int wid = tid >> 5;
    const int qg = qt * 128 + wid * 16;
    const int NT = Sc / 64;

    const uint4* Kh4 = (const uint4*)g_Kh + (size_t)bh * Sc * 8;
    const uint4* Kl4 = (const uint4*)g_Kl + (size_t)bh * Sc * 8;
    const uint4* Vf4 = (const uint4*)g_Vt + (size_t)bh * Dc * 256;

    auto load_kv = [&](int stg, int kt) {
        uint32_t base = sb + (stg * ABUFW) * 4;
        int kv0 = kt * 64;
        #pragma unroll
        for (int t = tid; t < 1536; t += 256) {
            int sec = t >> 9, rem = t & 511;
            int r = rem >> 3, q = rem & 7;
            if (sec == 0)
                cpa16(base + (KH0 + r * KPW + q * 4) * 4, Kh4 + (size_t)(kv0 + r) * 8 + q);
            else if (sec == 1)
                cpa16(base + (KL0 + r * KPW + q * 4) * 4, Kl4 + (size_t)(kv0 + r) * 8 + q);
            else
                cpa16(base + (VF0 + r * KPW + q * 4) * 4, Vf4 + (size_t)r * 256 + kt * 8 + q);
        }
    };

    uint32_t qh[4][4], ql[4][4];
    {
        const uint32_t* Qhw = (const uint32_t*)g_Qh + (size_t)bh * Sc * 32;
        const uint32_t* Qlw = (const uint32_t*)g_Ql + (size_t)bh * Sc * 32;
        int r0 = qg + (lane >> 2);
        #pragma unroll
        for (int s = 0; s < 4; s++) {
            int w0 = s * 8 + (lane & 3);
            qh[s][0] = Qhw[(size_t)r0 * 32 + w0];
            qh[s][1] = Qhw[(size_t)(r0 + 8) * 32 + w0];
            qh[s][2] = Qhw[(size_t)r0 * 32 + w0 + 4];
            qh[s][3] = Qhw[(size_t)(r0 + 8) * 32 + w0 + 4];
            ql[s][0] = Qlw[(size_t)r0 * 32 + w0];
            ql[s][1] = Qlw[(size_t)(r0 + 8) * 32 + w0];
            ql[s][2] = Qlw[(size_t)r0 * 32 + w0 + 4];
            ql[s][3] = Qlw[(size_t)(r0 + 8) * 32 + w0 + 4];
        }
    }

    float o[8][4];
    #pragma unroll
    for (int nd = 0; nd < 8; nd++)
        #pragma unroll
        for (int e = 0; e < 4; e++) o[nd][e] = 0.f;
    float lacc[4] = {0.f, 0.f, 0.f, 0.f};
    float m0 = -1e30f, m1 = -1e30f;

    const uint32_t ones_b = (lane < 4) ? 0x3C003C00u : 0u;

    const uint32_t f_row = (lane & 7) + ((lane & 16) >> 1);
    const uint32_t f_kw  = (lane & 8) >> 1;

    load_kv(0, 0); CPA_COMMIT();
    load_kv(1, 1); CPA_COMMIT();
    load_kv(2, 2); CPA_COMMIT();

    for (int kt = 0; kt < NT; kt++) {
        if (kt < NT - 2)      { CPA_WAIT(2); }
        else if (kt == NT - 2){ CPA_WAIT(1); }
        else                  { CPA_WAIT(0); }
        __syncthreads();
        if (kt + 3 < NT) { load_kv((kt + 3) % NSTAGE, kt + 3); CPA_COMMIT(); }

        uint32_t stage = sb + ((kt % NSTAGE) * ABUFW) * 4;

        // ---- scores: software-pipelined LDSM -> mma ----
        float sc[8][4];
        #pragma unroll
        for (int j = 0; j < 8; j++)
            #pragma unroll
            for (int e = 0; e < 4; e++) sc[j][e] = 0.f;

        uint32_t kf[2][8];
        {
            uint32_t ra = stage + (f_row * KPW + f_kw) * 4;     // idx 0: j2=0,s=0
            ldsm4(kf[0][0], kf[0][1], kf[0][2], kf[0][3], ra + KH0 * 4);
            ldsm4(kf[0][4], kf[0][5], kf[0][6], kf[0][7], ra + KL0 * 4);
        }
        #pragma unroll
        for (int idx = 0; idx < 16; idx++) {
            const int buf = idx & 1;
            if (idx + 1 < 16) {
                const int j2n = (idx + 1) >> 2, sn = (idx + 1) & 3;
                uint32_t ra = stage + ((j2n * 16 + f_row) * KPW + sn * 8 + f_kw) * 4;
                ldsm4(kf[buf ^ 1][0], kf[buf ^ 1][1], kf[buf ^ 1][2], kf[buf ^ 1][3], ra + KH0 * 4);
                ldsm4(kf[buf ^ 1][4], kf[buf ^ 1][5], kf[buf ^ 1][6], kf[buf ^ 1][7], ra + KL0 * 4);
            }
            const int j2 = idx >> 2, s = idx & 3;
            mma_bf16(sc[2 * j2],     qh[s], kf[buf][0], kf[buf][1]);
            mma_bf16(sc[2 * j2 + 1], qh[s], kf[buf][2], kf[buf][3]);
            mma_bf16(sc[2 * j2],     qh[s], kf[buf][4], kf[buf][5]);
            mma_bf16(sc[2 * j2 + 1], qh[s], kf[buf][6], kf[buf][7]);
            mma_bf16(sc[2 * j2],     ql[s], kf[buf][0], kf[buf][1]);
            mma_bf16(sc[2 * j2 + 1], ql[s], kf[buf][2], kf[buf][3]);
        }

        // ---- online softmax (base-2), rescale-skip ----
        float tm0 = -1e30f, tm1 = -1e30f;
        #pragma unroll
        for (int j = 0; j < 8; j++) {
            tm0 = fmaxf(tm0, fmaxf(sc[j][0], sc[j][1]));
            tm1 = fmaxf(tm1, fmaxf(sc[j][2], sc[j][3]));
        }
        tm0 = fmaxf(tm0, __shfl_xor_sync(0xffffffffu, tm0, 1));
        tm0 = fmaxf(tm0, __shfl_xor_sync(0xffffffffu, tm0, 2));
        tm1 = fmaxf(tm1, __shfl_xor_sync(0xffffffffu, tm1, 1));
        tm1 = fmaxf(tm1, __shfl_xor_sync(0xffffffffu, tm1, 2));
        bool upd = (tm0 > m0) | (tm1 > m1);
        if (__any_sync(0xffffffffu, upd)) {
            float mn0 = fmaxf(m0, tm0), mn1 = fmaxf(m1, tm1);
            float c0 = ex2f(m0 - mn0), c1 = ex2f(m1 - mn1);
            m0 = mn0; m1 = mn1;
            #pragma unroll
            for (int nd = 0; nd < 8; nd++) {
                o[nd][0] *= c0; o[nd][1] *= c0;
                o[nd][2] *= c1; o[nd][3] *= c1;
            }
            lacc[0] *= c0; lacc[1] *= c0;
            lacc[2] *= c1; lacc[3] *= c1;
        }

        uint32_t pk[8][2];
        #pragma unroll
        for (int j = 0; j < 8; j++) {
            pk[j][0] = ex2h2(packh2(sc[j][0] - m0, sc[j][1] - m0));
            pk[j][1] = ex2h2(packh2(sc[j][2] - m1, sc[j][3] - m1));
        }

        // ---- PV: software-pipelined; lacc mma interleaved per g ----
        uint32_t vf[2][4];
        {
            uint32_t ra = stage + (f_row * KPW + f_kw) * 4 + VF0 * 4;   // g=0,t=0
            ldsm4(vf[0][0], vf[0][1], vf[0][2], vf[0][3], ra);
        }
        #pragma unroll
        for (int idx = 0; idx < 16; idx++) {
            const int buf = idx & 1;
            if (idx + 1 < 16) {
                const int gn = (idx + 1) >> 2, tn = (idx + 1) & 3;
                uint32_t ra = stage + ((gn * 16 + f_row) * KPW + tn * 8 + f_kw) * 4 + VF0 * 4;
                ldsm4(vf[buf ^ 1][0], vf[buf ^ 1][1], vf[buf ^ 1][2], vf[buf ^ 1][3], ra);
            }
            const int g = idx >> 2, t = idx & 3;
            uint32_t a[4] = {pk[2 * t][0], pk[2 * t][1], pk[2 * t + 1][0], pk[2 * t + 1][1]};
            mma_f16(o[2 * g],     a, vf[buf][0], vf[buf][1]);
            mma_f16(o[2 * g + 1], a, vf[buf][2], vf[buf][3]);
            if (t == 3) {
                uint32_t al[4] = {pk[2 * g][0], pk[2 * g][1], pk[2 * g + 1][0], pk[2 * g + 1][1]};
                mma_f16(lacc, al, ones_b, ones_b);
            }
        }
    }

    float l0 = __shfl_sync(0xffffffffu, lacc[0], lane & ~3);
    float l1 = __shfl_sync(0xffffffffu, lacc[2], lane & ~3);
    float inv0 = 1.0f / l0, inv1 = 1.0f / l1;
    int r0 = qg + (lane >> 2);
    #pragma unroll
    for (int nd = 0; nd < 8; nd++) {
        int d = h * Dc + nd * 8 + 2 * (lane & 3);
        float2 v0 = make_float2(o[nd][0] * inv0, o[nd][1] * inv0);
        float2 v1 = make_float2(o[nd][2] * inv1, o[nd][3] * inv1);
        *(float2*)(out + ((size_t)b * Sc + r0) * 1024 + d)     = v0;
        *(float2*)(out + ((size_t)b * Sc + r0 + 8) * 1024 + d) = v1;
    }
}

// ---------------------------------------------------------------------------
extern "C" void kernel_launch(void* const* d_in, const int* in_sizes, int n_in,
                              void* d_out, int out_size) {
    const float* X    = (const float*)d_in[0];
    const float* W    = (const float*)d_in[1];
    const float* bias = (const float*)d_in[2];
    float* out = (float*)d_out;

    split_xw_kernel<<<4096 + 3072, 256>>>(X, W);

    cudaFuncSetAttribute(qkv_mma_kernel, cudaFuncAttributeMaxDynamicSharedMemorySize, QKV_SMEM);
    qkv_mma_kernel<<<dim3(NQKc / 128, MROWS / 128), 256, QKV_SMEM>>>(bias);

    cudaFuncSetAttribute(v_mma_kernel, cudaFuncAttributeMaxDynamicSharedMemorySize, VG_SMEM);
    v_mma_kernel<<<dim3(1024 / 128, MROWS / 128), 256, VG_SMEM>>>(bias);

    cudaFuncSetAttribute(attn_kernel, cudaFuncAttributeMaxDynamicSharedMemorySize, ATTN_SMEM);
    attn_kernel<<<dim3(Sc / 128, Hc, Bc), 256, ATTN_SMEM>>>(out);
}